// round 4
// baseline (speedup 1.0000x reference)
#include <cuda_runtime.h>
#include <cstdint>

// Row layout: [x, y, w, h, obj_conf, cls_0 .. cls_79]  (85 floats per row)
// Outputs: detections [total,7] fp32, then valid [total] (fp32 1/0 or uint8).

#define ROW_LEN 85
#define CONF_THRES 0.05f

__global__ __launch_bounds__(256) void postproc_kernel(
    const float* __restrict__ pred,
    float* __restrict__ det,          // [total, 7]
    float* __restrict__ valid_f,      // [total] if float mode, else nullptr
    uint8_t* __restrict__ valid_b,    // [total] if bool mode, else nullptr
    int total)
{
    __shared__ float sbuf[8][4 * ROW_LEN];     // per-warp staging: 4 rows = 340 floats

    const int lane = threadIdx.x & 31;
    const int wid  = threadIdx.x >> 5;         // warp in block (0..7)
    const int sub  = lane & 7;                 // lane within 8-lane group (one row)
    const int grp  = lane >> 3;                // 0..3: which row of this warp

    const long long warp0 = ((long long)blockIdx.x * 8 + wid) * 4;  // warp's first row
    const long long r = warp0 + grp;
    const bool wvalid = (r < (long long)total);

    float e0, m;
    unsigned mi;

    if (warp0 + 4 <= (long long)total) {
        // ---- fast path: stage 4 rows via 3 coalesced LDG.128 + STS.128 ----
        // byte offset warp0*340 is 16B-aligned (warp0 multiple of 4 -> 1360*k)
        const float4* __restrict__ g4 = (const float4*)(pred + warp0 * ROW_LEN);
        float4* s4 = (float4*)sbuf[wid];
        s4[lane]      = g4[lane];              // f4   0..31
        s4[lane + 32] = g4[lane + 32];         // f4  32..63
        if (lane < 21) s4[lane + 64] = g4[lane + 64];  // f4 64..84
        __syncwarp();

        // compute reads: immediate-offset LDS.32, stride 8 over this row
        const float* srow = sbuf[wid] + grp * ROW_LEN;
        e0 = srow[sub];                                    // elems 0..7
        m  = (sub >= 5) ? e0 : -1e30f;                     // classes 0..2
        mi = (unsigned)(sub - 5);
        #pragma unroll
        for (int k = 1; k < 10; k++) {
            float v = srow[sub + 8 * k];
            if (v > m) { m = v; mi = (unsigned)(sub + 8 * k - 5); }
        }
        if (sub < 5) {                                     // elems 80..84
            float v = srow[sub + 80];
            if (v > m) { m = v; mi = (unsigned)(sub + 75); }
        }
    } else {
        // ---- partial tail warp: direct LDG, clamp row so all lanes stay live ----
        const long long rr = wvalid ? r : (long long)(total - 1);
        const float* row = pred + rr * ROW_LEN;
        e0 = row[sub];
        m  = (sub >= 5) ? e0 : -1e30f;
        mi = (unsigned)(sub - 5);
        #pragma unroll
        for (int k = 1; k < 10; k++) {
            float v = row[sub + 8 * k];
            if (v > m) { m = v; mi = (unsigned)(sub + 8 * k - 5); }
        }
        if (sub < 5) {
            float v = row[sub + 80];
            if (v > m) { m = v; mi = (unsigned)(sub + 75); }
        }
    }

    // 8-lane group reduction via redux.sync (disjoint partition masks).
    // Class scores are uniform [0,1) -> non-negative -> u32-monotone bits.
    const unsigned gmask = 0xFFu << (lane & 24);
    const unsigned mb    = __float_as_uint(m);
    const unsigned maxb  = __reduce_max_sync(gmask, mb);
    const unsigned cand  = (mb == maxb) ? mi : 0xFFFFFFFFu;
    const unsigned gidx  = __reduce_min_sync(gmask, cand);  // first-occurrence argmax

    // obj_conf is element 4 of each row (group lane sub==4 holds it in e0).
    const float conf  = __shfl_sync(0xFFFFFFFFu, e0, (lane & 24) | 4);
    const bool  valid = (conf >= CONF_THRES);
    const float vf    = valid ? 1.0f : 0.0f;

    if (wvalid) {
        if (sub < 7) {
            float outv;
            if (sub < 5)       outv = e0 * vf;                    // x,y,w,h,conf
            else if (sub == 5) outv = __uint_as_float(maxb) * vf; // class_conf
            else               outv = (float)gidx * vf;           // class_id
            det[r * 7 + sub] = outv;
        } else {
            if (valid_f) valid_f[r] = vf;
            else         valid_b[r] = valid ? 1 : 0;
        }
    }
}

extern "C" void kernel_launch(void* const* d_in, const int* in_sizes, int n_in,
                              void* d_out, int out_size)
{
    const float* pred = (const float*)d_in[0];
    const int total = in_sizes[0] / ROW_LEN;   // B*N rows

    float* det = (float*)d_out;
    float* valid_f = nullptr;
    uint8_t* valid_b = nullptr;
    if (out_size == total * 8) {
        valid_f = det + (long long)total * 7;      // valid as 1.0/0.0 floats
    } else {
        valid_b = (uint8_t*)(det + (long long)total * 7);  // valid as bytes
    }

    // 4 rows per warp, 8 warps per block -> 32 rows per block
    const int rows_per_block = 32;
    const int blocks = (total + rows_per_block - 1) / rows_per_block;
    postproc_kernel<<<blocks, 256>>>(pred, det, valid_f, valid_b, total);
}

// round 5
// speedup vs baseline: 1.1289x; 1.1289x over previous
#include <cuda_runtime.h>
#include <cstdint>

// Row layout: [x, y, w, h, obj_conf, cls_0 .. cls_79]  (85 floats per row)
// Outputs: detections [total,7] fp32, then valid [total] (fp32 1/0 or uint8).

#define ROW_LEN 85
#define CONF_THRES 0.05f

#define ROWS_PER_WARP 4
#define WARPS_PER_BLOCK 8
#define ROWS_PER_STAGE (ROWS_PER_WARP * WARPS_PER_BLOCK)   // 32
#define STAGES 4
#define ROWS_PER_BLOCK (ROWS_PER_STAGE * STAGES)           // 128
#define STAGE_FLOATS (ROWS_PER_STAGE * ROW_LEN)            // 2720
#define STAGE_BYTES (STAGE_FLOATS * 4)                     // 10880 (mult of 16)

__device__ __forceinline__ unsigned smem_u32(const void* p) {
    unsigned a;
    asm("{ .reg .u64 t; cvta.to.shared.u64 t, %1; cvt.u32.u64 %0, t; }"
        : "=r"(a) : "l"(p));
    return a;
}

__device__ __forceinline__ void mbar_wait_parity(unsigned addr, unsigned parity) {
    asm volatile(
        "{\n\t"
        ".reg .pred P;\n\t"
        "WAIT_%=: \n\t"
        "mbarrier.try_wait.parity.acquire.cta.shared::cta.b64 P, [%0], %1, 0x989680;\n\t"
        "@P bra.uni DONE_%=;\n\t"
        "bra.uni WAIT_%=;\n\t"
        "DONE_%=:\n\t"
        "}"
        :: "r"(addr), "r"(parity) : "memory");
}

// Scan 85 floats of one row (strided by 8 over 8 lanes), return per-lane
// (max m, elem-of-e0, winning index). Same semantics as the proven R3 scan.
template <typename LoadF>
__device__ __forceinline__ void scan_row(LoadF ld, int sub,
                                         float& e0, float& m, unsigned& mi) {
    e0 = ld(sub);
    m  = (sub >= 5) ? e0 : -1e30f;     // classes 0..2 live in lanes 5..7
    int wk = 0;
    #pragma unroll
    for (int k = 1; k < 10; k++) {
        float v = ld(sub + 8 * k);
        if (v > m) { m = v; wk = k; }
    }
    if (sub < ROW_LEN - 80) {          // elems 80..84
        float v = ld(sub + 80);
        if (v > m) { m = v; wk = 10; }
    }
    mi = (unsigned)(sub - 5 + 8 * wk); // holds for all cases incl. wk=10
}

__global__ __launch_bounds__(256, 1) void postproc_kernel(
    const float* __restrict__ pred,
    float* __restrict__ det,          // [total, 7]
    float* __restrict__ valid_f,      // [total] if float mode, else nullptr
    uint8_t* __restrict__ valid_b,    // [total] if bool mode, else nullptr
    int total)
{
    __shared__ float sbuf[STAGES][STAGE_FLOATS];
    __shared__ __align__(8) unsigned long long mbar[STAGES];

    const int tid  = threadIdx.x;
    const int lane = tid & 31;
    const int wid  = tid >> 5;              // warp in block
    const int sub  = lane & 7;              // lane within 8-lane group
    const int grp  = lane >> 3;             // 0..3: row of this warp

    const long long blockRow0 = (long long)blockIdx.x * ROWS_PER_BLOCK;
    const bool full_block = (blockRow0 + ROWS_PER_BLOCK <= (long long)total);

    if (full_block) {
        // ---- producer: 4 async bulk copies, one per stage ----
        if (tid == 0) {
            #pragma unroll
            for (int s = 0; s < STAGES; s++) {
                unsigned mb = smem_u32(&mbar[s]);
                asm volatile("mbarrier.init.shared.b64 [%0], %1;"
                             :: "r"(mb), "r"(1u) : "memory");
            }
        }
        __syncthreads();
        asm volatile("fence.proxy.async.shared::cta;" ::: "memory");
        if (tid == 0) {
            const char* gsrc = (const char*)(pred + blockRow0 * ROW_LEN);
            #pragma unroll
            for (int s = 0; s < STAGES; s++) {
                unsigned mb = smem_u32(&mbar[s]);
                unsigned sd = smem_u32(&sbuf[s][0]);
                asm volatile(
                    "mbarrier.arrive.expect_tx.shared.b64 _, [%0], %1;"
                    :: "r"(mb), "r"((unsigned)STAGE_BYTES) : "memory");
                asm volatile(
                    "cp.async.bulk.shared::cta.global.mbarrier::complete_tx::bytes "
                    "[%0], [%1], %2, [%3];"
                    :: "r"(sd), "l"(gsrc + (size_t)s * STAGE_BYTES),
                       "r"((unsigned)STAGE_BYTES), "r"(mb) : "memory");
            }
        }

        // ---- consumers: each warp processes its 4 rows per stage ----
        #pragma unroll
        for (int s = 0; s < STAGES; s++) {
            mbar_wait_parity(smem_u32(&mbar[s]), 0u);

            const float* srow = &sbuf[s][(wid * ROWS_PER_WARP + grp) * ROW_LEN];
            float e0, m; unsigned mi;
            scan_row([&](int i) { return srow[i]; }, sub, e0, m, mi);

            // 8-lane group reduction (disjoint partition masks; scores >= 0
            // so float bits are u32-monotone).
            const unsigned gmask = 0xFFu << (lane & 24);
            const unsigned mb    = __float_as_uint(m);
            const unsigned maxb  = __reduce_max_sync(gmask, mb);
            const unsigned cand  = (mb == maxb) ? mi : 0xFFFFFFFFu;
            const unsigned gidx  = __reduce_min_sync(gmask, cand);

            const float conf  = __shfl_sync(0xFFFFFFFFu, e0, (lane & 24) | 4);
            const float vf    = (conf >= CONF_THRES) ? 1.0f : 0.0f;

            const long long r = blockRow0 + s * ROWS_PER_STAGE
                              + wid * ROWS_PER_WARP + grp;
            if (sub < 7) {
                float outv;
                if (sub < 5)       outv = e0 * vf;
                else if (sub == 5) outv = __uint_as_float(maxb) * vf;
                else               outv = (float)gidx * vf;
                det[r * 7 + sub] = outv;
            } else {
                if (valid_f) valid_f[r] = vf;
                else         valid_b[r] = (vf != 0.0f) ? 1 : 0;
            }
        }
    } else {
        // ---- partial tail block: direct-LDG path (proven R3 logic) ----
        #pragma unroll 1
        for (int s = 0; s < STAGES; s++) {
            const long long r = blockRow0 + s * ROWS_PER_STAGE
                              + wid * ROWS_PER_WARP + grp;
            const bool wvalid = (r < (long long)total);
            const long long rr = wvalid ? r : (long long)(total - 1);
            const float* row = pred + rr * ROW_LEN;

            float e0, m; unsigned mi;
            scan_row([&](int i) { return row[i]; }, sub, e0, m, mi);

            const unsigned gmask = 0xFFu << (lane & 24);
            const unsigned mb    = __float_as_uint(m);
            const unsigned maxb  = __reduce_max_sync(gmask, mb);
            const unsigned cand  = (mb == maxb) ? mi : 0xFFFFFFFFu;
            const unsigned gidx  = __reduce_min_sync(gmask, cand);

            const float conf  = __shfl_sync(0xFFFFFFFFu, e0, (lane & 24) | 4);
            const float vf    = (conf >= CONF_THRES) ? 1.0f : 0.0f;

            if (wvalid) {
                if (sub < 7) {
                    float outv;
                    if (sub < 5)       outv = e0 * vf;
                    else if (sub == 5) outv = __uint_as_float(maxb) * vf;
                    else               outv = (float)gidx * vf;
                    det[r * 7 + sub] = outv;
                } else {
                    if (valid_f) valid_f[r] = vf;
                    else         valid_b[r] = (vf != 0.0f) ? 1 : 0;
                }
            }
        }
    }
}

extern "C" void kernel_launch(void* const* d_in, const int* in_sizes, int n_in,
                              void* d_out, int out_size)
{
    const float* pred = (const float*)d_in[0];
    const int total = in_sizes[0] / ROW_LEN;   // B*N rows

    float* det = (float*)d_out;
    float* valid_f = nullptr;
    uint8_t* valid_b = nullptr;
    if (out_size == total * 8) {
        valid_f = det + (long long)total * 7;      // valid as 1.0/0.0 floats
    } else {
        valid_b = (uint8_t*)(det + (long long)total * 7);  // valid as bytes
    }

    const int blocks = (int)(((long long)total + ROWS_PER_BLOCK - 1) / ROWS_PER_BLOCK);
    postproc_kernel<<<blocks, 256>>>(pred, det, valid_f, valid_b, total);
}

// round 6
// speedup vs baseline: 1.1392x; 1.0091x over previous
#include <cuda_runtime.h>
#include <cstdint>

// Row layout: [x, y, w, h, obj_conf, cls_0 .. cls_79]  (85 floats per row)
// Outputs: detections [total,7] fp32, then valid [total] (fp32 1/0 or uint8).

#define ROW_LEN 85
#define CONF_THRES 0.05f

#define ROWS_PER_WARP 4
#define WARPS_PER_BLOCK 8
#define ROWS_PER_STAGE (ROWS_PER_WARP * WARPS_PER_BLOCK)   // 32
#define STAGES 2
#define ROWS_PER_BLOCK (ROWS_PER_STAGE * STAGES)           // 64
#define STAGE_FLOATS (ROWS_PER_STAGE * ROW_LEN)            // 2720
#define STAGE_BYTES (STAGE_FLOATS * 4)                     // 10880 (mult of 16)

__device__ __forceinline__ unsigned smem_u32(const void* p) {
    unsigned a;
    asm("{ .reg .u64 t; cvta.to.shared.u64 t, %1; cvt.u32.u64 %0, t; }"
        : "=r"(a) : "l"(p));
    return a;
}

__device__ __forceinline__ void mbar_wait_parity(unsigned addr, unsigned parity) {
    asm volatile(
        "{\n\t"
        ".reg .pred P;\n\t"
        "WAIT_%=: \n\t"
        "mbarrier.try_wait.parity.acquire.cta.shared::cta.b64 P, [%0], %1, 0x989680;\n\t"
        "@P bra.uni DONE_%=;\n\t"
        "bra.uni WAIT_%=;\n\t"
        "DONE_%=:\n\t"
        "}"
        :: "r"(addr), "r"(parity) : "memory");
}

// Scan 85 floats of one row (strided by 8 over 8 lanes), return per-lane
// (e0, max m, winning class index). Proven R3/R5 semantics.
template <typename LoadF>
__device__ __forceinline__ void scan_row(LoadF ld, int sub,
                                         float& e0, float& m, unsigned& mi) {
    e0 = ld(sub);
    m  = (sub >= 5) ? e0 : -1e30f;     // classes 0..2 live in lanes 5..7
    int wk = 0;
    #pragma unroll
    for (int k = 1; k < 10; k++) {
        float v = ld(sub + 8 * k);
        if (v > m) { m = v; wk = k; }
    }
    if (sub < ROW_LEN - 80) {          // elems 80..84
        float v = ld(sub + 80);
        if (v > m) { m = v; wk = 10; }
    }
    mi = (unsigned)(sub - 5 + 8 * wk);
}

__global__ __launch_bounds__(256) void postproc_kernel(
    const float* __restrict__ pred,
    float* __restrict__ det,          // [total, 7]
    float* __restrict__ valid_f,      // [total] if float mode, else nullptr
    uint8_t* __restrict__ valid_b,    // [total] if bool mode, else nullptr
    int total)
{
    __shared__ float sbuf[STAGES][STAGE_FLOATS];
    __shared__ __align__(8) unsigned long long mbar[STAGES];

    const int tid  = threadIdx.x;
    const int lane = tid & 31;
    const int wid  = tid >> 5;              // warp in block
    const int sub  = lane & 7;              // lane within 8-lane group
    const int grp  = lane >> 3;             // 0..3: row of this warp

    const long long blockRow0 = (long long)blockIdx.x * ROWS_PER_BLOCK;
    const bool full_block = (blockRow0 + ROWS_PER_BLOCK <= (long long)total);

    if (full_block) {
        // ---- producer: prefetch both stages via async bulk copy ----
        if (tid == 0) {
            #pragma unroll
            for (int s = 0; s < STAGES; s++) {
                unsigned mb = smem_u32(&mbar[s]);
                asm volatile("mbarrier.init.shared.b64 [%0], %1;"
                             :: "r"(mb), "r"(1u) : "memory");
            }
        }
        __syncthreads();
        asm volatile("fence.proxy.async.shared::cta;" ::: "memory");
        if (tid == 0) {
            const char* gsrc = (const char*)(pred + blockRow0 * ROW_LEN);
            #pragma unroll
            for (int s = 0; s < STAGES; s++) {
                unsigned mb = smem_u32(&mbar[s]);
                unsigned sd = smem_u32(&sbuf[s][0]);
                asm volatile(
                    "mbarrier.arrive.expect_tx.shared.b64 _, [%0], %1;"
                    :: "r"(mb), "r"((unsigned)STAGE_BYTES) : "memory");
                asm volatile(
                    "cp.async.bulk.shared::cta.global.mbarrier::complete_tx::bytes "
                    "[%0], [%1], %2, [%3];"
                    :: "r"(sd), "l"(gsrc + (size_t)s * STAGE_BYTES),
                       "r"((unsigned)STAGE_BYTES), "r"(mb) : "memory");
            }
        }

        // ---- consumers: each warp processes its 4 rows per stage ----
        #pragma unroll
        for (int s = 0; s < STAGES; s++) {
            mbar_wait_parity(smem_u32(&mbar[s]), 0u);

            const float* srow = &sbuf[s][(wid * ROWS_PER_WARP + grp) * ROW_LEN];
            float e0, m; unsigned mi;
            scan_row([&](int i) { return srow[i]; }, sub, e0, m, mi);

            // 8-lane group reduction (disjoint partition masks; scores >= 0
            // so float bits are u32-monotone).
            const unsigned gmask = 0xFFu << (lane & 24);
            const unsigned mb    = __float_as_uint(m);
            const unsigned maxb  = __reduce_max_sync(gmask, mb);
            const unsigned cand  = (mb == maxb) ? mi : 0xFFFFFFFFu;
            const unsigned gidx  = __reduce_min_sync(gmask, cand);

            const float conf  = __shfl_sync(0xFFFFFFFFu, e0, (lane & 24) | 4);
            const float vf    = (conf >= CONF_THRES) ? 1.0f : 0.0f;

            const long long r = blockRow0 + s * ROWS_PER_STAGE
                              + wid * ROWS_PER_WARP + grp;
            if (sub < 7) {
                float outv;
                if (sub < 5)       outv = e0 * vf;
                else if (sub == 5) outv = __uint_as_float(maxb) * vf;
                else               outv = (float)gidx * vf;
                det[r * 7 + sub] = outv;
            } else {
                if (valid_f) valid_f[r] = vf;
                else         valid_b[r] = (vf != 0.0f) ? 1 : 0;
            }
        }
    } else {
        // ---- partial tail block: direct-LDG path (proven R3 logic) ----
        #pragma unroll 1
        for (int s = 0; s < STAGES; s++) {
            const long long r = blockRow0 + s * ROWS_PER_STAGE
                              + wid * ROWS_PER_WARP + grp;
            const bool wvalid = (r < (long long)total);
            const long long rr = wvalid ? r : (long long)(total - 1);
            const float* row = pred + rr * ROW_LEN;

            float e0, m; unsigned mi;
            scan_row([&](int i) { return row[i]; }, sub, e0, m, mi);

            const unsigned gmask = 0xFFu << (lane & 24);
            const unsigned mb    = __float_as_uint(m);
            const unsigned maxb  = __reduce_max_sync(gmask, mb);
            const unsigned cand  = (mb == maxb) ? mi : 0xFFFFFFFFu;
            const unsigned gidx  = __reduce_min_sync(gmask, cand);

            const float conf  = __shfl_sync(0xFFFFFFFFu, e0, (lane & 24) | 4);
            const float vf    = (conf >= CONF_THRES) ? 1.0f : 0.0f;

            if (wvalid) {
                if (sub < 7) {
                    float outv;
                    if (sub < 5)       outv = e0 * vf;
                    else if (sub == 5) outv = __uint_as_float(maxb) * vf;
                    else               outv = (float)gidx * vf;
                    det[r * 7 + sub] = outv;
                } else {
                    if (valid_f) valid_f[r] = vf;
                    else         valid_b[r] = (vf != 0.0f) ? 1 : 0;
                }
            }
        }
    }
}

extern "C" void kernel_launch(void* const* d_in, const int* in_sizes, int n_in,
                              void* d_out, int out_size)
{
    const float* pred = (const float*)d_in[0];
    const int total = in_sizes[0] / ROW_LEN;   // B*N rows

    float* det = (float*)d_out;
    float* valid_f = nullptr;
    uint8_t* valid_b = nullptr;
    if (out_size == total * 8) {
        valid_f = det + (long long)total * 7;      // valid as 1.0/0.0 floats
    } else {
        valid_b = (uint8_t*)(det + (long long)total * 7);  // valid as bytes
    }

    const int blocks = (int)(((long long)total + ROWS_PER_BLOCK - 1) / ROWS_PER_BLOCK);
    postproc_kernel<<<blocks, 256>>>(pred, det, valid_f, valid_b, total);
}

// round 7
// speedup vs baseline: 1.1775x; 1.0336x over previous
#include <cuda_runtime.h>
#include <cstdint>

// Row layout: [x, y, w, h, obj_conf, cls_0 .. cls_79]  (85 floats per row)
// Outputs: detections [total,7] fp32, then valid [total] (fp32 1/0 or uint8).

#define ROW_LEN 85
#define CONF_THRES 0.05f

#define ROWS_PER_WARP 4
#define WARPS_PER_BLOCK 8
#define ROWS_PER_STAGE (ROWS_PER_WARP * WARPS_PER_BLOCK)   // 32
#define STAGES 2
#define ROWS_PER_BLOCK (ROWS_PER_STAGE * STAGES)           // 64
#define STAGE_FLOATS (ROWS_PER_STAGE * ROW_LEN)            // 2720
#define STAGE_BYTES (STAGE_FLOATS * 4)                     // 10880 (mult of 16)

__device__ __forceinline__ unsigned smem_u32(const void* p) {
    unsigned a;
    asm("{ .reg .u64 t; cvta.to.shared.u64 t, %1; cvt.u32.u64 %0, t; }"
        : "=r"(a) : "l"(p));
    return a;
}

__device__ __forceinline__ void mbar_wait_parity(unsigned addr, unsigned parity) {
    asm volatile(
        "{\n\t"
        ".reg .pred P;\n\t"
        "WAIT_%=: \n\t"
        "mbarrier.try_wait.parity.acquire.cta.shared::cta.b64 P, [%0], %1, 0x989680;\n\t"
        "@P bra.uni DONE_%=;\n\t"
        "bra.uni WAIT_%=;\n\t"
        "DONE_%=:\n\t"
        "}"
        :: "r"(addr), "r"(parity) : "memory");
}

// Scan 85 floats of one row (strided by 8 over 8 lanes), return per-lane
// (e0, max m, winning class index). Proven R3/R5 semantics.
template <typename LoadF>
__device__ __forceinline__ void scan_row(LoadF ld, int sub,
                                         float& e0, float& m, unsigned& mi) {
    e0 = ld(sub);
    m  = (sub >= 5) ? e0 : -1e30f;     // classes 0..2 live in lanes 5..7
    int wk = 0;
    #pragma unroll
    for (int k = 1; k < 10; k++) {
        float v = ld(sub + 8 * k);
        if (v > m) { m = v; wk = k; }
    }
    if (sub < ROW_LEN - 80) {          // elems 80..84
        float v = ld(sub + 80);
        if (v > m) { m = v; wk = 10; }
    }
    mi = (unsigned)(sub - 5 + 8 * wk);
}

__global__ __launch_bounds__(256) void postproc_kernel(
    const float* __restrict__ pred,
    float* __restrict__ det,          // [total, 7]
    float* __restrict__ valid_f,      // [total] if float mode, else nullptr
    uint8_t* __restrict__ valid_b,    // [total] if bool mode, else nullptr
    int total)
{
    __shared__ float sbuf[STAGES][STAGE_FLOATS];
    __shared__ __align__(8) unsigned long long mbar[STAGES];

    const int tid  = threadIdx.x;
    const int lane = tid & 31;
    const int wid  = tid >> 5;              // warp in block
    const int sub  = lane & 7;              // lane within 8-lane group
    const int grp  = lane >> 3;             // 0..3: which of this warp's rows

    // Bank-conflict-free mapping: warp wid handles rows {wid + 8*grp} within
    // each 32-row stage. Row delta 8 -> smem bank offset (8*85*grp) mod 32 =
    // {0,8,16,24}; with sub 0..7 the 4 groups tile all 32 banks exactly.
    const int rowInStage = wid + 8 * grp;

    const long long blockRow0 = (long long)blockIdx.x * ROWS_PER_BLOCK;
    const bool full_block = (blockRow0 + ROWS_PER_BLOCK <= (long long)total);

    if (full_block) {
        // ---- producer: prefetch both stages via async bulk copy ----
        if (tid == 0) {
            #pragma unroll
            for (int s = 0; s < STAGES; s++) {
                unsigned mb = smem_u32(&mbar[s]);
                asm volatile("mbarrier.init.shared.b64 [%0], %1;"
                             :: "r"(mb), "r"(1u) : "memory");
            }
        }
        __syncthreads();
        asm volatile("fence.proxy.async.shared::cta;" ::: "memory");
        if (tid == 0) {
            const char* gsrc = (const char*)(pred + blockRow0 * ROW_LEN);
            #pragma unroll
            for (int s = 0; s < STAGES; s++) {
                unsigned mb = smem_u32(&mbar[s]);
                unsigned sd = smem_u32(&sbuf[s][0]);
                asm volatile(
                    "mbarrier.arrive.expect_tx.shared.b64 _, [%0], %1;"
                    :: "r"(mb), "r"((unsigned)STAGE_BYTES) : "memory");
                asm volatile(
                    "cp.async.bulk.shared::cta.global.mbarrier::complete_tx::bytes "
                    "[%0], [%1], %2, [%3];"
                    :: "r"(sd), "l"(gsrc + (size_t)s * STAGE_BYTES),
                       "r"((unsigned)STAGE_BYTES), "r"(mb) : "memory");
            }
        }

        // ---- consumers: each warp processes its 4 rows per stage ----
        #pragma unroll
        for (int s = 0; s < STAGES; s++) {
            mbar_wait_parity(smem_u32(&mbar[s]), 0u);

            const float* srow = &sbuf[s][rowInStage * ROW_LEN];
            float e0, m; unsigned mi;
            scan_row([&](int i) { return srow[i]; }, sub, e0, m, mi);

            // 8-lane group reduction (disjoint partition masks; scores >= 0
            // so float bits are u32-monotone).
            const unsigned gmask = 0xFFu << (lane & 24);
            const unsigned mb    = __float_as_uint(m);
            const unsigned maxb  = __reduce_max_sync(gmask, mb);
            const unsigned cand  = (mb == maxb) ? mi : 0xFFFFFFFFu;
            const unsigned gidx  = __reduce_min_sync(gmask, cand);

            const float conf  = __shfl_sync(0xFFFFFFFFu, e0, (lane & 24) | 4);
            const float vf    = (conf >= CONF_THRES) ? 1.0f : 0.0f;

            const long long r = blockRow0 + s * ROWS_PER_STAGE + rowInStage;
            if (sub < 7) {
                float outv;
                if (sub < 5)       outv = e0 * vf;
                else if (sub == 5) outv = __uint_as_float(maxb) * vf;
                else               outv = (float)gidx * vf;
                det[r * 7 + sub] = outv;
            } else {
                if (valid_f) valid_f[r] = vf;
                else         valid_b[r] = (vf != 0.0f) ? 1 : 0;
            }
        }
    } else {
        // ---- partial tail block: direct-LDG path (proven R3 logic) ----
        #pragma unroll 1
        for (int s = 0; s < STAGES; s++) {
            const long long r = blockRow0 + s * ROWS_PER_STAGE + rowInStage;
            const bool wvalid = (r < (long long)total);
            const long long rr = wvalid ? r : (long long)(total - 1);
            const float* row = pred + rr * ROW_LEN;

            float e0, m; unsigned mi;
            scan_row([&](int i) { return row[i]; }, sub, e0, m, mi);

            const unsigned gmask = 0xFFu << (lane & 24);
            const unsigned mb    = __float_as_uint(m);
            const unsigned maxb  = __reduce_max_sync(gmask, mb);
            const unsigned cand  = (mb == maxb) ? mi : 0xFFFFFFFFu;
            const unsigned gidx  = __reduce_min_sync(gmask, cand);

            const float conf  = __shfl_sync(0xFFFFFFFFu, e0, (lane & 24) | 4);
            const float vf    = (conf >= CONF_THRES) ? 1.0f : 0.0f;

            if (wvalid) {
                if (sub < 7) {
                    float outv;
                    if (sub < 5)       outv = e0 * vf;
                    else if (sub == 5) outv = __uint_as_float(maxb) * vf;
                    else               outv = (float)gidx * vf;
                    det[r * 7 + sub] = outv;
                } else {
                    if (valid_f) valid_f[r] = vf;
                    else         valid_b[r] = (vf != 0.0f) ? 1 : 0;
                }
            }
        }
    }
}

extern "C" void kernel_launch(void* const* d_in, const int* in_sizes, int n_in,
                              void* d_out, int out_size)
{
    const float* pred = (const float*)d_in[0];
    const int total = in_sizes[0] / ROW_LEN;   // B*N rows

    float* det = (float*)d_out;
    float* valid_f = nullptr;
    uint8_t* valid_b = nullptr;
    if (out_size == total * 8) {
        valid_f = det + (long long)total * 7;      // valid as 1.0/0.0 floats
    } else {
        valid_b = (uint8_t*)(det + (long long)total * 7);  // valid as bytes
    }

    const int blocks = (int)(((long long)total + ROWS_PER_BLOCK - 1) / ROWS_PER_BLOCK);
    postproc_kernel<<<blocks, 256>>>(pred, det, valid_f, valid_b, total);
}